// round 4
// baseline (speedup 1.0000x reference)
#include <cuda_runtime.h>

// DropBlock fused persistent kernel.
// x [64,256,64,64] f32, u [58,58] f32. BLOCK_SIZE=7, DROP_PROB=0.1.
// Every CTA independently computes the 64x64 multiplier table (mask*scale)
// from u via bitboards (deterministic, cheap), then grid-strides the
// 268MB elementwise multiply.

#define H 64
#define W 64
#define HW 4096
#define US 58           // H - BS + 1
#define BS 7
#define DROP_PROB 0.1f

#define THREADS 256
#define BLOCKS  (148 * 8)   // persistent grid: 8 CTAs/SM on 148 SMs

__global__ __launch_bounds__(THREADS)
void dropblock_fused_kernel(const float* __restrict__ u,
                            const float4* __restrict__ x4,
                            float4* __restrict__ out4,
                            int n4) {
    __shared__ unsigned long long s_drop[US];
    __shared__ unsigned long long s_hdil[US];
    __shared__ unsigned long long s_vdil[H];
    __shared__ int s_sum;
    // 16 KB multiplier table — MUST be 16B-aligned: read via LDS.128
    __shared__ __align__(16) float s_mult[HW];

    int tid = threadIdx.x;

    // ---- Phase 1: build mask (bitboards) ----
    if (tid < US) s_drop[tid] = 0ULL;
    if (tid == 0) s_sum = 0;
    __syncthreads();

    for (int p = tid; p < US * US; p += THREADS) {
        int i = p / US;
        int j = p - i * US;
        if (__ldg(&u[p]) < DROP_PROB)
            atomicOr(&s_drop[i], 1ULL << j);
    }
    __syncthreads();

    if (tid < US) {
        unsigned long long b = s_drop[tid];
        unsigned long long h = b;
        #pragma unroll
        for (int s = 1; s < BS; s++) h |= b << s;
        s_hdil[tid] = h;
    }
    __syncthreads();

    if (tid < H) {
        int y = tid;
        int i0 = y - (BS - 1); if (i0 < 0) i0 = 0;
        int i1 = y;            if (i1 > US - 1) i1 = US - 1;
        unsigned long long v = 0ULL;
        for (int i = i0; i <= i1; i++) v |= s_hdil[i];
        s_vdil[y] = v;
        int keep = W - __popcll(v);
        #pragma unroll
        for (int off = 16; off > 0; off >>= 1)
            keep += __shfl_down_sync(0xFFFFFFFFu, keep, off);
        if ((tid & 31) == 0) atomicAdd(&s_sum, keep);
    }
    __syncthreads();

    float scale = (float)HW / (float)s_sum;

    for (int p = tid; p < HW; p += THREADS) {
        int y = p >> 6;
        int x = p & 63;
        s_mult[p] = ((s_vdil[y] >> x) & 1ULL) ? 0.0f : scale;
    }
    __syncthreads();

    // ---- Phase 2: grid-stride streaming multiply ----
    const float4* m4 = reinterpret_cast<const float4*>(s_mult);
    int S = gridDim.x * THREADS;                 // total threads
    int base = blockIdx.x * THREADS + tid;

    int i = base;
    // 4-way unrolled main loop (independent iterations -> batched LDGs)
    for (; i + 3 * S < n4; i += 4 * S) {
        int ia = i, ib = i + S, ic = i + 2 * S, id = i + 3 * S;
        float4 va = __ldcs(&x4[ia]);
        float4 vb = __ldcs(&x4[ib]);
        float4 vc = __ldcs(&x4[ic]);
        float4 vd = __ldcs(&x4[id]);
        float4 ma = m4[ia & 1023];
        float4 mb = m4[ib & 1023];
        float4 mc = m4[ic & 1023];
        float4 md = m4[id & 1023];
        va.x *= ma.x; va.y *= ma.y; va.z *= ma.z; va.w *= ma.w;
        vb.x *= mb.x; vb.y *= mb.y; vb.z *= mb.z; vb.w *= mb.w;
        vc.x *= mc.x; vc.y *= mc.y; vc.z *= mc.z; vc.w *= mc.w;
        vd.x *= md.x; vd.y *= md.y; vd.z *= md.z; vd.w *= md.w;
        __stcs(&out4[ia], va);
        __stcs(&out4[ib], vb);
        __stcs(&out4[ic], vc);
        __stcs(&out4[id], vd);
    }
    for (; i < n4; i += S) {
        float4 v = __ldcs(&x4[i]);
        float4 m = m4[i & 1023];
        v.x *= m.x; v.y *= m.y; v.z *= m.z; v.w *= m.w;
        __stcs(&out4[i], v);
    }
}

extern "C" void kernel_launch(void* const* d_in, const int* in_sizes, int n_in,
                              void* d_out, int out_size) {
    const float* x = (const float*)d_in[0];
    const float* u = (const float*)d_in[1];
    float* out = (float*)d_out;

    int n4 = out_size / 4;   // 16,777,216 float4s
    dropblock_fused_kernel<<<BLOCKS, THREADS>>>(
        u, (const float4*)x, (float4*)out, n4);
}

// round 5
// speedup vs baseline: 1.1437x; 1.1437x over previous
#include <cuda_runtime.h>

// DropBlock: x [64,256,64,64] f32, u [58,58] f32. BLOCK_SIZE=7, DROP_PROB=0.1
// Two kernels linked by PDL (programmatic dependent launch):
//   k1: bitboard mask -> d_mult (4096 floats), triggers PDL immediately.
//   k2: streaming multiply; front-loads x (independent of mask), then
//       cudaGridDependencySynchronize() before reading d_mult.

#define H 64
#define W 64
#define HW 4096
#define US 58           // H - BS + 1
#define BS 7
#define DROP_PROB 0.1f

__device__ __align__(16) float d_mult[HW];

// ---------------- Kernel 1: build multiplier table (bitboards) ----------------
__global__ void build_mask_kernel(const float* __restrict__ u) {
    // let the dependent kernel start launching right away
    cudaTriggerProgrammaticLaunchCompletion();

    __shared__ unsigned long long s_drop[US];
    __shared__ unsigned long long s_hdil[US];
    __shared__ unsigned long long s_vdil[H];
    __shared__ int s_sum;
    __shared__ float s_scale;

    int tid = threadIdx.x;

    if (tid < US) s_drop[tid] = 0ULL;
    if (tid == 0) s_sum = 0;
    __syncthreads();

    for (int p = tid; p < US * US; p += 1024) {
        int i = p / US;
        int j = p - i * US;
        if (__ldg(&u[p]) < DROP_PROB)
            atomicOr(&s_drop[i], 1ULL << j);
    }
    __syncthreads();

    if (tid < US) {
        unsigned long long b = s_drop[tid];
        unsigned long long h = b;
        #pragma unroll
        for (int s = 1; s < BS; s++) h |= b << s;
        s_hdil[tid] = h;
    }
    __syncthreads();

    if (tid < H) {
        int y = tid;
        int i0 = y - (BS - 1); if (i0 < 0) i0 = 0;
        int i1 = y;            if (i1 > US - 1) i1 = US - 1;
        unsigned long long v = 0ULL;
        for (int i = i0; i <= i1; i++) v |= s_hdil[i];
        s_vdil[y] = v;
        int keep = W - __popcll(v);
        #pragma unroll
        for (int off = 16; off > 0; off >>= 1)
            keep += __shfl_down_sync(0xFFFFFFFFu, keep, off);
        if ((tid & 31) == 0) atomicAdd(&s_sum, keep);
    }
    __syncthreads();

    if (tid == 0) s_scale = (float)HW / (float)s_sum;
    __syncthreads();
    float scale = s_scale;

    for (int p = tid; p < HW; p += 1024) {
        int y = p >> 6;
        int x = p & 63;
        d_mult[p] = ((s_vdil[y] >> x) & 1ULL) ? 0.0f : scale;
    }
}

// ---------------- Kernel 2: streaming multiply (PDL consumer) ----------------
// R1 config (1 float4/thread) measured best BW (6163 GB/s).
__global__ void apply_mask_kernel(const float4* __restrict__ x4,
                                  float4* __restrict__ out4,
                                  int n4) {
    int idx = blockIdx.x * blockDim.x + threadIdx.x;
    bool valid = idx < n4;

    // Independent of kernel1's output: issue the big global read NOW,
    // overlapping kernel1's execution in the first wave.
    float4 v;
    if (valid) v = __ldcs(&x4[idx]);

    // Wait for kernel1 completion (d_mult visible).
    cudaGridDependencySynchronize();

    if (!valid) return;
    const float4* m4 = reinterpret_cast<const float4*>(d_mult);
    float4 m = __ldg(&m4[idx & 1023]);
    v.x *= m.x; v.y *= m.y; v.z *= m.z; v.w *= m.w;
    __stcs(&out4[idx], v);
}

extern "C" void kernel_launch(void* const* d_in, const int* in_sizes, int n_in,
                              void* d_out, int out_size) {
    const float* x = (const float*)d_in[0];
    const float* u = (const float*)d_in[1];
    float* out = (float*)d_out;

    build_mask_kernel<<<1, 1024>>>(u);

    int n4 = out_size / 4;               // 16,777,216 float4s
    int threads = 256;
    int blocks = (n4 + threads - 1) / threads;

    // Launch k2 with programmatic stream serialization (PDL edge).
    cudaLaunchConfig_t cfg = {};
    cfg.gridDim = dim3(blocks, 1, 1);
    cfg.blockDim = dim3(threads, 1, 1);
    cfg.dynamicSmemBytes = 0;
    cfg.stream = 0;
    cudaLaunchAttribute attr[1];
    attr[0].id = cudaLaunchAttributeProgrammaticStreamSerialization;
    attr[0].val.programmaticStreamSerializationAllowed = 1;
    cfg.attrs = attr;
    cfg.numAttrs = 1;

    cudaLaunchKernelEx(&cfg, apply_mask_kernel,
                       (const float4*)x, (float4*)out, n4);
}